// round 4
// baseline (speedup 1.0000x reference)
#include <cuda_runtime.h>
#include <cuda_bf16.h>

// Shapes (fixed): B=16, TE=TD=128, H=256
#define Bsz 16
#define TT 128
#define HH 256
#define MROWS (Bsz*TT)   // 2048

typedef unsigned long long u64;

// Scratch (device globals; no allocation allowed)
__device__ float g_enc[MROWS*HH];   // orthogonalized encoder [B*TE][H]
__device__ float g_was[MROWS*HH];   // enc_ortho @ W_a
__device__ float g_uah[MROWS*HH];   // dec @ U_a

__device__ __forceinline__ float tanh_fast(float x) {
    float y;
    asm("tanh.approx.f32 %0, %1;" : "=f"(y) : "f"(x));
    return y;
}
__device__ __forceinline__ u64 pack2(float lo, float hi) {
    u64 r; asm("mov.b64 %0, {%1, %2};" : "=l"(r) : "f"(lo), "f"(hi)); return r;
}
__device__ __forceinline__ void unpack2(u64 v, float& a, float& b) {
    asm("mov.b64 {%0, %1}, %2;" : "=f"(a), "=f"(b) : "l"(v));
}
// d = a*b + d on packed f32x2 (Blackwell FFMA2)
__device__ __forceinline__ void fma2(u64& d, u64 a, u64 b) {
    asm("fma.rn.f32x2 %0, %1, %2, %0;" : "+l"(d) : "l"(a), "l"(b));
}

// ---------------------------------------------------------------------------
// K1: orthogonalize. grid 64 = (b * 4 + hblock), block 256 = 4 segs x 64 h
// ---------------------------------------------------------------------------
__global__ __launch_bounds__(256) void ortho_kernel(const float* __restrict__ enc) {
    int b  = blockIdx.x >> 2;
    int hb = blockIdx.x & 3;
    int tid = threadIdx.x;
    int seg = tid >> 6;          // 0..3 (32 timesteps each)
    int hh  = tid & 63;
    int h = hb * 64 + hh;
    const float* base = enc + (b * TT) * HH + h;
    float* obase = g_enc + (b * TT) * HH + h;
    int t0 = seg * 32;

    float ps = 0.f;
    #pragma unroll 4
    for (int t = 0; t < 32; t++) ps += base[(t0 + t) * HH];

    __shared__ float part[4][64];
    part[seg][hh] = ps;
    __syncthreads();

    float run = 0.f;
    for (int s2 = 0; s2 < seg; s2++) run += part[s2][hh];

    #pragma unroll 4
    for (int t = 0; t < 32; t++) {
        float x = base[(t0 + t) * HH];
        float s = run;
        float o = x - ((x * s) / (x * x)) * x;
        obase[(t0 + t) * HH] = o;
        run += x;
    }
}

// ---------------------------------------------------------------------------
// K2: two GEMMs [2048,256]@[256,256]. BM=128 BN=64 BK=32, 512 threads,
// 4m x 4n microtile with f32x2 packed FMA (pairs along M), register prefetch.
// grid (16, 4, 2) = 128 CTAs, 16 warps/SM.
// z=0: g_enc @ W_a -> g_was ; z=1: dec @ U_a -> g_uah
// ---------------------------------------------------------------------------
#define BMP 132
#define BNP 68
__global__ __launch_bounds__(512) void gemm2_kernel(const float* __restrict__ dec,
                                                    const float* __restrict__ Wa,
                                                    const float* __restrict__ Ua) {
    const float *A, *W;
    float *C;
    if (blockIdx.z == 0) { A = g_enc; W = Wa; C = g_was; }
    else                 { A = dec;   W = Ua; C = g_uah; }

    __shared__ __align__(16) float As[32 * BMP];
    __shared__ __align__(16) float Bs[32 * BNP];

    int tid = threadIdx.x;
    int mblk = blockIdx.x * 128;
    int nblk = blockIdx.y * 64;

    float4 pa[2], pb;

    #define LOADT(kt) { \
        _Pragma("unroll") \
        for (int q = 0; q < 2; q++) { int s = tid + q * 512; int m = s >> 3, kq = s & 7; \
            pa[q] = *(const float4*)&A[(mblk + m) * HH + (kt) * 32 + kq * 4]; } \
        { int k = tid >> 4, nq = tid & 15; \
            pb = *(const float4*)&W[((kt) * 32 + k) * HH + nblk + nq * 4]; } }

    int tr = tid >> 4, tc = tid & 15;   // tr 0..31, tc 0..15
    int m0 = tr * 4, n0 = tc * 4;
    u64 acc2[2][4] = {};   // 2 m-pairs x 4 n

    LOADT(0);
    for (int kt = 0; kt < 8; kt++) {
        __syncthreads();
        #pragma unroll
        for (int q = 0; q < 2; q++) {
            int s = tid + q * 512; int m = s >> 3, kq = s & 7;
            As[(kq * 4 + 0) * BMP + m] = pa[q].x;
            As[(kq * 4 + 1) * BMP + m] = pa[q].y;
            As[(kq * 4 + 2) * BMP + m] = pa[q].z;
            As[(kq * 4 + 3) * BMP + m] = pa[q].w;
        }
        {
            int k = tid >> 4, nq = tid & 15;
            *(float4*)&Bs[k * BNP + nq * 4] = pb;
        }
        __syncthreads();
        if (kt < 7) LOADT(kt + 1);

        #pragma unroll 8
        for (int kk = 0; kk < 32; kk++) {
            ulonglong2 aA = *(const ulonglong2*)&As[kk * BMP + m0];
            float4 bb = *(const float4*)&Bs[kk * BNP + n0];
            u64 b0 = pack2(bb.x, bb.x);
            u64 b1 = pack2(bb.y, bb.y);
            u64 b2 = pack2(bb.z, bb.z);
            u64 b3 = pack2(bb.w, bb.w);
            fma2(acc2[0][0], aA.x, b0); fma2(acc2[0][1], aA.x, b1);
            fma2(acc2[0][2], aA.x, b2); fma2(acc2[0][3], aA.x, b3);
            fma2(acc2[1][0], aA.y, b0); fma2(acc2[1][1], aA.y, b1);
            fma2(acc2[1][2], aA.y, b2); fma2(acc2[1][3], aA.y, b3);
        }
    }
    #pragma unroll
    for (int i = 0; i < 2; i++) {
        float lo[4], hi[4];
        #pragma unroll
        for (int j = 0; j < 4; j++) unpack2(acc2[i][j], lo[j], hi[j]);
        float4 o0 = {lo[0], lo[1], lo[2], lo[3]};
        float4 o1 = {hi[0], hi[1], hi[2], hi[3]};
        *(float4*)&C[(mblk + m0 + 2 * i) * HH + nblk + n0] = o0;
        *(float4*)&C[(mblk + m0 + 2 * i + 1) * HH + nblk + n0] = o1;
    }
    #undef LOADT
}

// ---------------------------------------------------------------------------
// K3: energy + softmax. grid (8 dblocks, 16 b), block 512 (16 warps).
// SMEM: was_t [256][132] transposed, uah_t [256][20], V [256].
// Warp w owns d-row w: energy row computed in regs, softmax via shuffles.
// ---------------------------------------------------------------------------
__global__ __launch_bounds__(512) void energy_softmax_kernel(const float* __restrict__ Va,
                                                             float* __restrict__ eo) {
    extern __shared__ float sm3[];
    float* was_t = sm3;                  // 256*132
    float* uah_t = was_t + 256 * 132;    // 256*20
    float* Vs    = uah_t + 256 * 20;     // 256

    int db = blockIdx.x;
    int b  = blockIdx.y;
    int tid = threadIdx.x;

    for (int idx = tid; idx < TT * HH; idx += 512) {
        int e = idx >> 8, h = idx & 255;
        was_t[h * 132 + e] = g_was[(b * TT + e) * HH + h];
    }
    for (int idx = tid; idx < 16 * HH; idx += 512) {
        int dd = idx >> 8, h = idx & 255;
        uah_t[h * 20 + dd] = g_uah[(b * TT + db * 16 + dd) * HH + h];
    }
    if (tid < 256) Vs[tid] = Va[tid];
    __syncthreads();

    int eg = tid & 31, dg = tid >> 5;    // dg = warp = d-row (0..15)
    int e0 = eg * 4;
    const float* wp = was_t + e0;
    const float* up = uah_t + dg;

    float a0 = 0.f, a1 = 0.f, a2 = 0.f, a3 = 0.f;
    #pragma unroll 4
    for (int h = 0; h < HH; h++) {
        float4 w4 = *(const float4*)(wp + h * 132);
        float u = up[h * 20];
        float v = Vs[h];
        a0 += v * tanh_fast(u + w4.x);
        a1 += v * tanh_fast(u + w4.y);
        a2 += v * tanh_fast(u + w4.z);
        a3 += v * tanh_fast(u + w4.w);
    }

    // warp softmax over the 128-wide row held across lanes (4 per lane)
    float m = fmaxf(fmaxf(a0, a1), fmaxf(a2, a3));
    #pragma unroll
    for (int o = 16; o > 0; o >>= 1) m = fmaxf(m, __shfl_xor_sync(0xffffffffu, m, o));
    float x0 = __expf(a0 - m), x1 = __expf(a1 - m);
    float x2 = __expf(a2 - m), x3 = __expf(a3 - m);
    float ssum = x0 + x1 + x2 + x3;
    #pragma unroll
    for (int o = 16; o > 0; o >>= 1) ssum += __shfl_xor_sync(0xffffffffu, ssum, o);
    float inv = 1.f / ssum;
    float4 o4 = {x0 * inv, x1 * inv, x2 * inv, x3 * inv};
    *(float4*)&eo[(b * TT + db * 16 + dg) * TT + e0] = o4;
}

// ---------------------------------------------------------------------------
// K4: batched GEMM c[b] = P[b](128x128) @ E[b](128x256).
// BM=64 (d), BN=64 (h), K=128 (e). grid (4 nb, 2 mb, 16 b) = 128 CTAs = 1 wave.
// 256 threads, 4m x 4n microtile; k-loop chunked by 8 with explicit register
// batch prefetch (MLP=16 LDS.128 in flight) to hide shared latency at 8 warps.
// ---------------------------------------------------------------------------
#define PMP 68
__global__ __launch_bounds__(256) void context_kernel(const float* __restrict__ eo,
                                                      float* __restrict__ co) {
    extern __shared__ float sm4[];
    float* Ps = sm4;              // [128 e][68 pad]  (m minor, transposed)
    float* Es = sm4 + 128 * PMP;  // [128 e][64 h]

    int nb = blockIdx.x, mb = blockIdx.y, b = blockIdx.z;
    int tid = threadIdx.x;

    // stage P^T: Ps[e][m] = eo[b, mb*64+m, e]
    #pragma unroll
    for (int t = tid; t < 64 * 128; t += 256) {
        int m = t >> 7, e = t & 127;
        Ps[e * PMP + m] = eo[(b * TT + mb * 64 + m) * TT + e];
    }
    // stage E: Es[e][h] = g_enc[b, e, nb*64+h]  (float4)
    #pragma unroll
    for (int t = tid; t < (128 * 64) / 4; t += 256) {
        int e = t >> 4, hq = t & 15;
        *(float4*)&Es[e * 64 + hq * 4] =
            *(const float4*)&g_enc[(b * TT + e) * HH + nb * 64 + hq * 4];
    }
    __syncthreads();

    int tr = tid >> 4, tc = tid & 15;
    int m0 = tr * 4, n0 = tc * 4;

    u64 acc2[2][4] = {};   // [m-pair][n]
    #pragma unroll 1
    for (int kc = 0; kc < 128; kc += 8) {
        ulonglong2 ap[8];
        float4 bv[8];
        #pragma unroll
        for (int j = 0; j < 8; j++) {
            ap[j] = *(const ulonglong2*)&Ps[(kc + j) * PMP + m0];
            bv[j] = *(const float4*)&Es[(kc + j) * 64 + n0];
        }
        #pragma unroll
        for (int j = 0; j < 8; j++) {
            u64 b0 = pack2(bv[j].x, bv[j].x);
            u64 b1 = pack2(bv[j].y, bv[j].y);
            u64 b2 = pack2(bv[j].z, bv[j].z);
            u64 b3 = pack2(bv[j].w, bv[j].w);
            fma2(acc2[0][0], ap[j].x, b0); fma2(acc2[0][1], ap[j].x, b1);
            fma2(acc2[0][2], ap[j].x, b2); fma2(acc2[0][3], ap[j].x, b3);
            fma2(acc2[1][0], ap[j].y, b0); fma2(acc2[1][1], ap[j].y, b1);
            fma2(acc2[1][2], ap[j].y, b2); fma2(acc2[1][3], ap[j].y, b3);
        }
    }

    #pragma unroll
    for (int i = 0; i < 2; i++) {
        float lo[4], hi[4];
        #pragma unroll
        for (int j = 0; j < 4; j++) unpack2(acc2[i][j], lo[j], hi[j]);
        float4 r0 = {lo[0], lo[1], lo[2], lo[3]};   // row m0+2i
        float4 r1 = {hi[0], hi[1], hi[2], hi[3]};   // row m0+2i+1
        *(float4*)&co[(b * TT + mb * 64 + m0 + 2 * i) * HH + nb * 64 + n0] = r0;
        *(float4*)&co[(b * TT + mb * 64 + m0 + 2 * i + 1) * HH + nb * 64 + n0] = r1;
    }
}

// ---------------------------------------------------------------------------
extern "C" void kernel_launch(void* const* d_in, const int* in_sizes, int n_in,
                              void* d_out, int out_size) {
    const float* enc = (const float*)d_in[0];
    const float* dec = (const float*)d_in[1];
    const float* Wa  = (const float*)d_in[2];
    const float* Ua  = (const float*)d_in[3];
    const float* Va  = (const float*)d_in[4];

    float* co = (float*)d_out;                    // c_outputs [16,128,256]
    float* eo = co + Bsz * TT * HH;               // e_outputs [16,128,128]

    const int SM3 = (256 * 132 + 256 * 20 + 256) * 4;   // 156672 B
    const int SM4 = (128 * PMP + 128 * 64) * 4;         // 67584 B
    static bool attr_done = false;
    if (!attr_done) {
        cudaFuncSetAttribute(energy_softmax_kernel,
                             cudaFuncAttributeMaxDynamicSharedMemorySize, SM3);
        cudaFuncSetAttribute(context_kernel,
                             cudaFuncAttributeMaxDynamicSharedMemorySize, SM4);
        attr_done = true;
    }

    ortho_kernel<<<64, 256>>>(enc);
    gemm2_kernel<<<dim3(16, 4, 2), 512>>>(dec, Wa, Ua);
    energy_softmax_kernel<<<dim3(8, 16), 512, SM3>>>(Va, eo);
    context_kernel<<<dim3(4, 2, 16), 256, SM4>>>(eo, co);
}

// round 6
// speedup vs baseline: 1.0691x; 1.0691x over previous
#include <cuda_runtime.h>
#include <cuda_bf16.h>

// Shapes (fixed): B=16, TE=TD=128, H=256
#define Bsz 16
#define TT 128
#define HH 256
#define MROWS (Bsz*TT)   // 2048

typedef unsigned long long u64;

// Scratch (device globals; no allocation allowed)
__device__ float g_enc[MROWS*HH];   // orthogonalized encoder [B*TE][H]
__device__ float g_was[MROWS*HH];   // enc_ortho @ W_a
__device__ float g_uah[MROWS*HH];   // dec @ U_a

__device__ __forceinline__ float tanh_fast(float x) {
    float y;
    asm("tanh.approx.f32 %0, %1;" : "=f"(y) : "f"(x));
    return y;
}
__device__ __forceinline__ u64 pack2(float lo, float hi) {
    u64 r; asm("mov.b64 %0, {%1, %2};" : "=l"(r) : "f"(lo), "f"(hi)); return r;
}
__device__ __forceinline__ void unpack2(u64 v, float& a, float& b) {
    asm("mov.b64 {%0, %1}, %2;" : "=f"(a), "=f"(b) : "l"(v));
}
// d = a*b + d on packed f32x2 (Blackwell FFMA2)
__device__ __forceinline__ void fma2(u64& d, u64 a, u64 b) {
    asm("fma.rn.f32x2 %0, %1, %2, %0;" : "+l"(d) : "l"(a), "l"(b));
}

// ---------------------------------------------------------------------------
// K1: orthogonalize. grid 64 = (b * 4 + hblock), block 256 = 4 segs x 64 h
// ---------------------------------------------------------------------------
__global__ __launch_bounds__(256) void ortho_kernel(const float* __restrict__ enc) {
    int b  = blockIdx.x >> 2;
    int hb = blockIdx.x & 3;
    int tid = threadIdx.x;
    int seg = tid >> 6;          // 0..3 (32 timesteps each)
    int hh  = tid & 63;
    int h = hb * 64 + hh;
    const float* base = enc + (b * TT) * HH + h;
    float* obase = g_enc + (b * TT) * HH + h;
    int t0 = seg * 32;

    float ps = 0.f;
    #pragma unroll 4
    for (int t = 0; t < 32; t++) ps += base[(t0 + t) * HH];

    __shared__ float part[4][64];
    part[seg][hh] = ps;
    __syncthreads();

    float run = 0.f;
    for (int s2 = 0; s2 < seg; s2++) run += part[s2][hh];

    #pragma unroll 4
    for (int t = 0; t < 32; t++) {
        float x = base[(t0 + t) * HH];
        float s = run;
        float o = x - ((x * s) / (x * x)) * x;
        obase[(t0 + t) * HH] = o;
        run += x;
    }
}

// ---------------------------------------------------------------------------
// K2: two GEMMs [2048,256]@[256,256]. BM=128 BN=64 BK=32, 8x4 microtile with
// f32x2 packed FMA (pairs along M), 256 threads, register prefetch.
// grid (16, 4, 2). z=0: g_enc @ W_a -> g_was ; z=1: dec @ U_a -> g_uah
// (R3 configuration — the 512-thread variant measured slower.)
// ---------------------------------------------------------------------------
#define BMP 132
#define BNP 68
__global__ __launch_bounds__(256) void gemm2_kernel(const float* __restrict__ dec,
                                                    const float* __restrict__ Wa,
                                                    const float* __restrict__ Ua) {
    const float *A, *W;
    float *C;
    if (blockIdx.z == 0) { A = g_enc; W = Wa; C = g_was; }
    else                 { A = dec;   W = Ua; C = g_uah; }

    __shared__ __align__(16) float As[32 * BMP];
    __shared__ __align__(16) float Bs[32 * BNP];

    int tid = threadIdx.x;
    int mblk = blockIdx.x * 128;
    int nblk = blockIdx.y * 64;

    float4 pa[4], pb[2];

    #define LOADT(kt) { \
        _Pragma("unroll") \
        for (int q = 0; q < 4; q++) { int s = tid + q * 256; int m = s >> 3, kq = s & 7; \
            pa[q] = *(const float4*)&A[(mblk + m) * HH + (kt) * 32 + kq * 4]; } \
        _Pragma("unroll") \
        for (int q = 0; q < 2; q++) { int s = tid + q * 256; int k = s >> 4, nq = s & 15; \
            pb[q] = *(const float4*)&W[((kt) * 32 + k) * HH + nblk + nq * 4]; } }

    int tr = tid >> 4, tc = tid & 15;
    int m0 = tr * 8, n0 = tc * 4;
    u64 acc2[4][4] = {};   // 4 m-pairs x 4 n

    LOADT(0);
    for (int kt = 0; kt < 8; kt++) {
        __syncthreads();
        #pragma unroll
        for (int q = 0; q < 4; q++) {
            int s = tid + q * 256; int m = s >> 3, kq = s & 7;
            As[(kq * 4 + 0) * BMP + m] = pa[q].x;
            As[(kq * 4 + 1) * BMP + m] = pa[q].y;
            As[(kq * 4 + 2) * BMP + m] = pa[q].z;
            As[(kq * 4 + 3) * BMP + m] = pa[q].w;
        }
        #pragma unroll
        for (int q = 0; q < 2; q++) {
            int s = tid + q * 256; int k = s >> 4, nq = s & 15;
            *(float4*)&Bs[k * BNP + nq * 4] = pb[q];
        }
        __syncthreads();
        if (kt < 7) LOADT(kt + 1);

        #pragma unroll
        for (int kk = 0; kk < 32; kk++) {
            ulonglong2 aA = *(const ulonglong2*)&As[kk * BMP + m0];
            ulonglong2 aB = *(const ulonglong2*)&As[kk * BMP + m0 + 4];
            float4 bb = *(const float4*)&Bs[kk * BNP + n0];
            u64 am2[4] = {aA.x, aA.y, aB.x, aB.y};
            u64 bn2[4] = {pack2(bb.x, bb.x), pack2(bb.y, bb.y),
                          pack2(bb.z, bb.z), pack2(bb.w, bb.w)};
            #pragma unroll
            for (int i = 0; i < 4; i++)
                #pragma unroll
                for (int j = 0; j < 4; j++)
                    fma2(acc2[i][j], am2[i], bn2[j]);
        }
    }
    #pragma unroll
    for (int i = 0; i < 4; i++) {
        float lo[4], hi[4];
        #pragma unroll
        for (int j = 0; j < 4; j++) unpack2(acc2[i][j], lo[j], hi[j]);
        float4 o0 = {lo[0], lo[1], lo[2], lo[3]};
        float4 o1 = {hi[0], hi[1], hi[2], hi[3]};
        *(float4*)&C[(mblk + m0 + 2 * i) * HH + nblk + n0] = o0;
        *(float4*)&C[(mblk + m0 + 2 * i + 1) * HH + nblk + n0] = o1;
    }
    #undef LOADT
}

// ---------------------------------------------------------------------------
// K3 (fused): energy + softmax + context. grid (8 dblocks, 16 b), block 512.
// Phase 1: energy rows in regs (warp dg owns d-row dg), warp softmax, write eo.
// Phase 2: reuse SMEM — stage P^T[16][128] + E[128][256] (overwrites was_t),
//          block GEMM C[16,256] = P @ E, write co.
// ---------------------------------------------------------------------------
__global__ __launch_bounds__(512) void energy_ctx_kernel(const float* __restrict__ Va,
                                                         float* __restrict__ eo,
                                                         float* __restrict__ co) {
    extern __shared__ float sm3[];
    // phase-1 layout
    float* was_t = sm3;                  // 256*132 = 33792 floats
    float* uah_t = was_t + 256 * 132;    // 256*20  (ends at 38912)
    float* Vs    = uah_t + 256 * 20;     // 256
    // phase-2 layout (aliases phase-1, valid after the mid-kernel barrier)
    float* Es = sm3;                     // [128 e][256 h] = 32768 floats
    float* Pt = sm3 + 32768;             // [16 d][128 e]  = 2048 floats

    int db = blockIdx.x;
    int b  = blockIdx.y;
    int tid = threadIdx.x;

    for (int idx = tid; idx < TT * HH; idx += 512) {
        int e = idx >> 8, h = idx & 255;
        was_t[h * 132 + e] = g_was[(b * TT + e) * HH + h];
    }
    for (int idx = tid; idx < 16 * HH; idx += 512) {
        int dd = idx >> 8, h = idx & 255;
        uah_t[h * 20 + dd] = g_uah[(b * TT + db * 16 + dd) * HH + h];
    }
    if (tid < 256) Vs[tid] = Va[tid];
    __syncthreads();

    int eg = tid & 31, dg = tid >> 5;    // dg = warp = d-row (0..15)
    int e0 = eg * 4;
    const float* wp = was_t + e0;
    const float* up = uah_t + dg;

    float a0 = 0.f, a1 = 0.f, a2 = 0.f, a3 = 0.f;
    #pragma unroll 4
    for (int h = 0; h < HH; h++) {
        float4 w4 = *(const float4*)(wp + h * 132);
        float u = up[h * 20];
        float v = Vs[h];
        a0 += v * tanh_fast(u + w4.x);
        a1 += v * tanh_fast(u + w4.y);
        a2 += v * tanh_fast(u + w4.z);
        a3 += v * tanh_fast(u + w4.w);
    }

    // warp softmax over the 128-wide row (4 values per lane)
    float m = fmaxf(fmaxf(a0, a1), fmaxf(a2, a3));
    #pragma unroll
    for (int o = 16; o > 0; o >>= 1) m = fmaxf(m, __shfl_xor_sync(0xffffffffu, m, o));
    float x0 = __expf(a0 - m), x1 = __expf(a1 - m);
    float x2 = __expf(a2 - m), x3 = __expf(a3 - m);
    float ssum = x0 + x1 + x2 + x3;
    #pragma unroll
    for (int o = 16; o > 0; o >>= 1) ssum += __shfl_xor_sync(0xffffffffu, ssum, o);
    float inv = 1.f / ssum;
    float4 p4 = {x0 * inv, x1 * inv, x2 * inv, x3 * inv};
    *(float4*)&eo[(b * TT + db * 16 + dg) * TT + e0] = p4;

    // ---- phase 2: context ----
    __syncthreads();   // all reads of was_t/uah_t complete before aliasing

    // P^T: warp dg writes its row (lane-consecutive -> conflict-free)
    *(float4*)&Pt[dg * 128 + e0] = p4;
    // stage E (overwrites was_t region)
    #pragma unroll
    for (int t = tid; t < (TT * HH) / 4; t += 512) {
        int e = t >> 6, hq = t & 63;
        *(float4*)&Es[e * HH + hq * 4] =
            *(const float4*)&g_enc[(b * TT + e) * HH + hq * 4];
    }
    __syncthreads();

    // block GEMM: C[16,256] = P[16,128] @ E[128,256]
    // thread map: mp = tid>>6 (0..7) -> rows (2*mp, 2*mp+1); tc = tid&63 -> cols 4*tc
    int mp = tid >> 6, tc = tid & 63;
    int m0 = mp * 2, n0 = tc * 4;
    const float* p0r = Pt + m0 * 128;
    const float* p1r = Pt + (m0 + 1) * 128;
    const float* er  = Es + n0;

    u64 acc2[2][2] = {};   // [m][n-pair]
    #pragma unroll 4
    for (int k = 0; k < 128; k++) {
        float pv0 = p0r[k];              // LDS.32 broadcast
        float pv1 = p1r[k];
        ulonglong2 ev = *(const ulonglong2*)(er + k * HH);   // (n0,n0+1),(n0+2,n0+3)
        u64 pa0 = pack2(pv0, pv0);
        u64 pa1 = pack2(pv1, pv1);
        fma2(acc2[0][0], pa0, ev.x); fma2(acc2[0][1], pa0, ev.y);
        fma2(acc2[1][0], pa1, ev.x); fma2(acc2[1][1], pa1, ev.y);
    }

    #pragma unroll
    for (int i = 0; i < 2; i++) {
        float l0, h0, l1, h1;
        unpack2(acc2[i][0], l0, h0);
        unpack2(acc2[i][1], l1, h1);
        float4 r = {l0, h0, l1, h1};
        *(float4*)&co[(b * TT + db * 16 + m0 + i) * HH + n0] = r;
    }
}

// ---------------------------------------------------------------------------
extern "C" void kernel_launch(void* const* d_in, const int* in_sizes, int n_in,
                              void* d_out, int out_size) {
    const float* enc = (const float*)d_in[0];
    const float* dec = (const float*)d_in[1];
    const float* Wa  = (const float*)d_in[2];
    const float* Ua  = (const float*)d_in[3];
    const float* Va  = (const float*)d_in[4];

    float* co = (float*)d_out;                    // c_outputs [16,128,256]
    float* eo = co + Bsz * TT * HH;               // e_outputs [16,128,128]

    const int SM3 = (256 * 132 + 256 * 20 + 256) * 4;   // 156672 B (covers both phases)
    static bool attr_done = false;
    if (!attr_done) {
        cudaFuncSetAttribute(energy_ctx_kernel,
                             cudaFuncAttributeMaxDynamicSharedMemorySize, SM3);
        attr_done = true;
    }

    ortho_kernel<<<64, 256>>>(enc);
    gemm2_kernel<<<dim3(16, 4, 2), 256>>>(dec, Wa, Ua);
    energy_ctx_kernel<<<dim3(8, 16), 512, SM3>>>(Va, eo, co);
}